// round 1
// baseline (speedup 1.0000x reference)
#include <cuda_runtime.h>
#include <cstdint>

// ---------------- problem constants ----------------
#define MF    1024            // frag points
#define NCC   512             // cloud points per batch
#define KSN   24              // kernel points
#define NAN_  60              // anchors
#define CON   128             // out channels
#define NBB   2               // batch
#define R2C   0.16f           // RADIUS^2
// S = log2(e)/SIGMA
#define SCV   18.033688011112043f
#define EPSV  1e-5f

#define FEAT_OFF  (NBB*3*NCC)                 // 3072
#define FEAT_N    (NBB*CON*NCC*NAN_)          // 7864320
#define ANCH_OFF  (FEAT_OFF + FEAT_N)         // 7867392
#define GRP       (NCC*NAN_)                  // 30720 elements per (b,c)

__device__ float g_sum[NBB*CON];
__device__ float g_sqs[NBB*CON];

__device__ __forceinline__ float ex2f(float x) {
    float r; asm("ex2.approx.ftz.f32 %0, %1;" : "=f"(r) : "f"(x)); return r;
}

__global__ void zero_kernel() {
    int t = threadIdx.x;
    if (t < NBB*CON) { g_sum[t] = 0.f; g_sqs[t] = 0.f; }
}

// One CTA = (cloud point, anchor-half). 128 threads.
__global__ void __launch_bounds__(128) prop_kernel(
    const float* __restrict__ frag,    // [1024,3]
    const float* __restrict__ clouds,  // [2,3,512]
    const float* __restrict__ kern,    // [24,60,3]
    const float* __restrict__ W,       // [128,24]
    float* __restrict__ out)
{
    __shared__ float4 listbuf[MF];        // phase A/B: compacted frags; phase C: reuse as feat stage
    __shared__ float  wts_s[30][24];
    __shared__ int    sc[128];

    const int tid   = threadIdx.x;
    const int blk   = blockIdx.x;
    const int point = blk >> 1;
    const int half  = blk & 1;
    const int b     = point >> 9;        // /512
    const int n     = point & (NCC-1);

    const float cx = clouds[b*3*NCC +           n];
    const float cy = clouds[b*3*NCC +   NCC   + n];
    const float cz = clouds[b*3*NCC + 2*NCC   + n];

    // ---------- Phase A: deterministic masked-frag compaction ----------
    // Each thread owns 8 contiguous frags (24 contiguous floats -> 6 x LDG.128).
    float fr[24];
    {
        const float4* fp = reinterpret_cast<const float4*>(frag) + tid*6;
        #pragma unroll
        for (int u = 0; u < 6; u++) {
            float4 q = fp[u];
            fr[u*4+0] = q.x; fr[u*4+1] = q.y; fr[u*4+2] = q.z; fr[u*4+3] = q.w;
        }
    }
    float lx[8], ly[8], lz[8], lp[8];
    unsigned pm = 0;
    #pragma unroll
    for (int j = 0; j < 8; j++) {
        float dx = fr[j*3+0] - cx;
        float dy = fr[j*3+1] - cy;
        float dz = fr[j*3+2] - cz;
        float d2 = dx*dx + dy*dy + dz*dz;
        lx[j] = dx; ly[j] = dy; lz[j] = dz; lp[j] = -d2 * SCV;
        if (d2 < R2C) pm |= (1u << j);
    }
    int c0 = __popc(pm);
    sc[tid] = c0;
    __syncthreads();
    // Hillis-Steele inclusive scan over 128 per-thread counts
    #pragma unroll
    for (int off = 1; off < 128; off <<= 1) {
        int v = sc[tid];
        int u = (tid >= off) ? sc[tid-off] : 0;
        __syncthreads();
        sc[tid] = v + u;
        __syncthreads();
    }
    int ofs = sc[tid] - c0;
    const int cnt = sc[127];
    #pragma unroll
    for (int j = 0; j < 8; j++) {
        if (pm & (1u << j)) { listbuf[ofs++] = make_float4(lx[j], ly[j], lz[j], lp[j]); }
    }
    __syncthreads();

    // ---------- Phase B: RBF accumulation ----------
    // Thread role: a_local = tid/4 (0..29 active), owns 6 kernel points (tid%4)*6 ..
    const float invc = 1.0f / (float)(cnt + 1);
    const int a_local = tid >> 2;
    const int kq      = tid & 3;
    if (a_local < 30) {
        const int a = half*30 + a_local;
        float kxr[6], kyr[6], kzr[6], cf[6], acc[6];
        #pragma unroll
        for (int j = 0; j < 6; j++) {
            int k = kq*6 + j;
            const float* kp = kern + ((size_t)k*NAN_ + a)*3;
            float rx = kp[0], ry = kp[1], rz = kp[2];
            float k2 = rx*rx + ry*ry + rz*rz;
            cf[j]  = ex2f(-k2 * SCV);             // exp(-|kern|^2 / sigma)
            kxr[j] = rx * (2.0f*SCV);
            kyr[j] = ry * (2.0f*SCV);
            kzr[j] = rz * (2.0f*SCV);
            acc[j] = 0.f;
        }
        const float4* lst = listbuf;
        int i = 0;
        #pragma unroll 1
        for (; i + 2 <= cnt; i += 2) {
            float4 v0 = lst[i];
            float4 v1 = lst[i+1];
            #pragma unroll
            for (int j = 0; j < 6; j++) {
                float t0 = fmaf(kxr[j], v0.x, fmaf(kyr[j], v0.y, fmaf(kzr[j], v0.z, v0.w)));
                float t1 = fmaf(kxr[j], v1.x, fmaf(kyr[j], v1.y, fmaf(kzr[j], v1.z, v1.w)));
                acc[j] += ex2f(t0);
                acc[j] += ex2f(t1);
            }
        }
        if (i < cnt) {
            float4 v0 = lst[i];
            #pragma unroll
            for (int j = 0; j < 6; j++) {
                float t0 = fmaf(kxr[j], v0.x, fmaf(kyr[j], v0.y, fmaf(kzr[j], v0.z, v0.w)));
                acc[j] += ex2f(t0);
            }
        }
        #pragma unroll
        for (int j = 0; j < 6; j++)
            wts_s[a_local][kq*6 + j] = acc[j] * cf[j] * invc;
    }
    __syncthreads();

    // ---------- Phase C: feats = W @ wts, partial stats, staged store ----------
    float wr[24];
    {
        const float* wp = W + tid*KSN;
        #pragma unroll
        for (int k = 0; k < 24; k++) wr[k] = wp[k];
    }
    float* fsm = reinterpret_cast<float*>(listbuf);   // 3840 floats <= 16KB
    float ls = 0.f, lss = 0.f;
    #pragma unroll 1
    for (int al = 0; al < 30; al++) {
        const float* wrow = &wts_s[al][0];            // broadcast reads
        float s = 0.f;
        #pragma unroll
        for (int k = 0; k < 24; k++) s = fmaf(wr[k], wrow[k], s);
        fsm[tid*30 + al] = s;
        ls  += s;
        lss  = fmaf(s, s, lss);
    }
    atomicAdd(&g_sum[b*CON + tid], ls);
    atomicAdd(&g_sqs[b*CON + tid], lss);
    __syncthreads();

    // Coalesced-ish store of 128x30 staged feats
    float* fout = out + FEAT_OFF;
    for (int e = tid; e < CON*30; e += 128) {
        int c  = e / 30;
        int al = e - c*30;
        int oidx = (((b*CON + c)*NCC) + n)*NAN_ + half*30 + al;
        fout[oidx] = fsm[e];
    }
}

// In-place normalize + ReLU, plus clouds/anchors passthrough copies.
__global__ void norm_kernel(const float* __restrict__ clouds,
                            const float* __restrict__ anchors,
                            float* __restrict__ out)
{
    int idx = blockIdx.x*256 + threadIdx.x;
    if (idx < FEAT_OFF) out[idx] = clouds[idx];
    if (idx < 540)      out[ANCH_OFF + idx] = anchors[idx];
    if (idx < FEAT_N) {
        int bc = idx / GRP;
        const float inv = 1.0f / (float)GRP;
        float mu  = g_sum[bc] * inv;
        float var = fmaf(-mu, mu, g_sqs[bc] * inv);
        float x = out[FEAT_OFF + idx];
        float y = (x - mu) * rsqrtf(var + EPSV);
        out[FEAT_OFF + idx] = fmaxf(y, 0.f);
    }
}

extern "C" void kernel_launch(void* const* d_in, const int* in_sizes, int n_in,
                              void* d_out, int out_size) {
    const float* frag    = (const float*)d_in[0];
    const float* clouds  = (const float*)d_in[1];
    const float* kern    = (const float*)d_in[2];
    const float* W       = (const float*)d_in[3];
    const float* anchors = (const float*)d_in[4];
    float* out = (float*)d_out;

    zero_kernel<<<1, 256>>>();
    prop_kernel<<<NBB*NCC*2, 128>>>(frag, clouds, kern, W, out);
    norm_kernel<<<(FEAT_N + 255)/256, 256>>>(clouds, anchors, out);
}